// round 13
// baseline (speedup 1.0000x reference)
#include <cuda_runtime.h>
#include <cuda_fp16.h>
#include <math.h>
#include <stdint.h>

#define D_MODEL 1024
#define N_HEADS 16
#define D_HEAD  64
#define BATCH   4
#define SEQ     2048
#define M_ROWS  (BATCH * SEQ)   // 8192

// ---------------- helpers ----------------
__device__ __forceinline__ uint32_t smem_u32(const void* p) {
    uint32_t a;
    asm("{ .reg .u64 t; cvta.to.shared.u64 t, %1; cvt.u32.u64 %0, t; }" : "=r"(a) : "l"(p));
    return a;
}
__device__ __forceinline__ uint32_t pack_h2(float lo, float hi) {
    uint32_t d; asm("cvt.rn.f16x2.f32 %0, %1, %2;" : "=r"(d) : "f"(hi), "f"(lo)); return d;
}
__device__ __forceinline__ void ldmatrix_x4(uint32_t* r, uint32_t addr) {
    asm volatile("ldmatrix.sync.aligned.m8n8.x4.shared.b16 {%0,%1,%2,%3}, [%4];"
        : "=r"(r[0]), "=r"(r[1]), "=r"(r[2]), "=r"(r[3]) : "r"(addr));
}
__device__ __forceinline__ void ldmatrix_x4_trans(uint32_t* r, uint32_t addr) {
    asm volatile("ldmatrix.sync.aligned.m8n8.x4.trans.shared.b16 {%0,%1,%2,%3}, [%4];"
        : "=r"(r[0]), "=r"(r[1]), "=r"(r[2]), "=r"(r[3]) : "r"(addr));
}
__device__ __forceinline__ void mma_f16(float* c, const uint32_t* a, uint32_t b0, uint32_t b1) {
    asm volatile("mma.sync.aligned.m16n8k16.row.col.f32.f16.f16.f32 "
        "{%0,%1,%2,%3}, {%4,%5,%6,%7}, {%8,%9}, {%0,%1,%2,%3};"
        : "+f"(c[0]), "+f"(c[1]), "+f"(c[2]), "+f"(c[3])
        : "r"(a[0]), "r"(a[1]), "r"(a[2]), "r"(a[3]), "r"(b0), "r"(b1));
}
__device__ __forceinline__ uint32_t sw128(uint32_t off) { return off ^ ((off >> 3) & 0x70); }
__device__ __forceinline__ void cp_async16(uint32_t s, const void* g) {
    asm volatile("cp.async.cg.shared.global [%0], [%1], 16;" :: "r"(s), "l"(g));
}
__device__ __forceinline__ void cp_commit() { asm volatile("cp.async.commit_group;" ::: "memory"); }
template<int N> __device__ __forceinline__ void cp_wait() {
    asm volatile("cp.async.wait_group %0;" :: "n"(N) : "memory");
}

// ---------------- scratch (half precision working set) ----------------
__device__ __half g_Xn[M_ROWS * D_MODEL];
__device__ __half g_Q [M_ROWS * D_MODEL];
__device__ __half g_K [M_ROWS * D_MODEL];
__device__ __half g_V [M_ROWS * D_MODEL];
__device__ __half g_O [M_ROWS * D_MODEL];
__device__ __half g_Wh[4 * D_MODEL * D_MODEL];   // Wq,Wk,Wv,Wo as fp16

// ---------------- fused LayerNorm + weight convert ----------------
__global__ __launch_bounds__(256) void ln_conv(
    const float* __restrict__ X, const float* __restrict__ gamma,
    const float* __restrict__ beta, __half* __restrict__ Xn,
    const float* __restrict__ Wq, const float* __restrict__ Wk,
    const float* __restrict__ Wv, const float* __restrict__ Wo,
    __half* __restrict__ Wh)
{
    int tid = threadIdx.x;
    if (blockIdx.x >= M_ROWS) {
        int idx = (blockIdx.x - M_ROWS) * 256 + tid;
        const float* src[4] = { Wq, Wk, Wv, Wo };
        #pragma unroll
        for (int w = 0; w < 4; w++) {
            float4 v = reinterpret_cast<const float4*>(src[w])[idx];
            uint2 o;
            o.x = pack_h2(v.x, v.y);
            o.y = pack_h2(v.z, v.w);
            reinterpret_cast<uint2*>(Wh + (size_t)w * D_MODEL * D_MODEL)[idx] = o;
        }
        return;
    }

    int row = blockIdx.x;
    const float4* xr = reinterpret_cast<const float4*>(X + (size_t)row * D_MODEL);
    float4 v = xr[tid];

    float s  = v.x + v.y + v.z + v.w;
    float sq = v.x*v.x + v.y*v.y + v.z*v.z + v.w*v.w;

    #pragma unroll
    for (int o = 16; o > 0; o >>= 1) {
        s  += __shfl_xor_sync(0xffffffffu, s,  o);
        sq += __shfl_xor_sync(0xffffffffu, sq, o);
    }
    __shared__ float ss[8], ssq[8];
    int wid = tid >> 5, lid = tid & 31;
    if (lid == 0) { ss[wid] = s; ssq[wid] = sq; }
    __syncthreads();
    if (wid == 0) {
        float a = (lid < 8) ? ss[lid]  : 0.f;
        float bb = (lid < 8) ? ssq[lid] : 0.f;
        #pragma unroll
        for (int o = 4; o > 0; o >>= 1) {
            a  += __shfl_xor_sync(0xffffffffu, a, o);
            bb += __shfl_xor_sync(0xffffffffu, bb, o);
        }
        if (lid == 0) { ss[0] = a; ssq[0] = bb; }
    }
    __syncthreads();
    float mean = ss[0] * (1.0f / D_MODEL);
    float var  = ssq[0] * (1.0f / D_MODEL) - mean * mean;
    float rstd = rsqrtf(var + 1e-5f);

    const float4* g4 = reinterpret_cast<const float4*>(gamma);
    const float4* b4 = reinterpret_cast<const float4*>(beta);
    float4 gv = g4[tid], bv = b4[tid];
    uint2 o;
    o.x = pack_h2((v.x - mean) * rstd * gv.x + bv.x, (v.y - mean) * rstd * gv.y + bv.y);
    o.y = pack_h2((v.z - mean) * rstd * gv.z + bv.z, (v.w - mean) * rstd * gv.w + bv.w);
    reinterpret_cast<uint2*>(Xn + (size_t)row * D_MODEL)[tid] = o;
}

// ---------------- persistent fp16 mma GEMM: C = (A @ W^T + bias) * cscale ----------------
// 3-stage cp.async, 128 regs, 2 CTAs/SM. Persistent: grid = 296 CTAs,
// each loops over 128x128 tiles (no wave quantization).
#define GSTG 32768   // stage = A tile 16KB + B tile 16KB
#define NPERS 296    // 148 SMs x 2 CTAs

__global__ __launch_bounds__(256, 2) void gemm_h(
    const __half* __restrict__ A, const __half* __restrict__ Wh, int w_off, int ntiles,
    const float* __restrict__ bias0, const float* __restrict__ bias1, const float* __restrict__ bias2,
    void* __restrict__ C0, void* __restrict__ C1, void* __restrict__ C2,
    int half_out, float qscale)
{
    extern __shared__ char sm[];
    uint32_t sbase = smem_u32(sm);

    const int tid = threadIdx.x;
    const int lane = tid & 31;
    const int wid = tid >> 5;
    const int warp_m = wid >> 2;
    const int warp_n = wid & 3;

    const int Lg = lane >> 3;
    const int Lr = lane & 7;
    const int a_row = ((Lg & 1) << 3) + Lr;
    const int a_byte = (Lg >> 1) << 4;
    const int b_row = Lr + ((Lg >> 1) << 3);
    const int b_byte = (Lg & 1) << 4;

    const int fr = tid >> 1;
    const int fj = (tid & 1) << 2;

    for (int t = blockIdx.x; t < ntiles; t += gridDim.x) {
        const int z  = t >> 9;          // 512 tiles per output
        const int r  = t & 511;
        const int bm = (r >> 3) * 128;
        const int bn = (r & 7) * 128;

        const __half* W = Wh + (size_t)(w_off + z) * D_MODEL * D_MODEL;
        const float* bias = (z == 0) ? bias0 : (z == 1) ? bias1 : bias2;
        void* C = (z == 0) ? C0 : (z == 1) ? C1 : C2;
        const float cscale = (z == 0) ? qscale : 1.0f;

        // all warps must be done reading the previous tile's smem
        __syncthreads();

        float acc[4][4][4];
        #pragma unroll
        for (int mt = 0; mt < 4; mt++)
            #pragma unroll
            for (int nt = 0; nt < 4; nt++)
                #pragma unroll
                for (int e = 0; e < 4; e++) acc[mt][nt][e] = 0.f;

        auto issue = [&](int kt) {
            uint32_t sa = sbase + (kt % 3) * GSTG;
            uint32_t sb2 = sa + 16384;
            const __half* Ag = A + (size_t)(bm + fr) * D_MODEL + kt * 64;
            const __half* Wg = W + (size_t)(bn + fr) * D_MODEL + kt * 64;
            #pragma unroll
            for (int q = 0; q < 4; q++) {
                int j = fj + q;
                uint32_t sw = sw128((uint32_t)(fr * 128 + j * 16));
                cp_async16(sa + sw, Ag + j * 8);
                cp_async16(sb2 + sw, Wg + j * 8);
            }
            cp_commit();
        };

        issue(0);
        issue(1);

        for (int kt = 0; kt < 16; kt++) {
            if (kt < 15) cp_wait<1>(); else cp_wait<0>();
            __syncthreads();
            if (kt + 2 < 16) issue(kt + 2);

            uint32_t abase = sbase + (kt % 3) * GSTG;
            uint32_t bbase = abase + 16384;

            #pragma unroll
            for (int ks = 0; ks < 4; ks++) {
                uint32_t af[4][4];
                #pragma unroll
                for (int mt = 0; mt < 4; mt++)
                    ldmatrix_x4(af[mt], abase + sw128(
                        (uint32_t)((warp_m * 64 + mt * 16 + a_row) * 128 + ks * 32 + a_byte)));
                uint32_t bfr[2][4];
                #pragma unroll
                for (int np = 0; np < 2; np++)
                    ldmatrix_x4(bfr[np], bbase + sw128(
                        (uint32_t)((warp_n * 32 + np * 16 + b_row) * 128 + ks * 32 + b_byte)));
                #pragma unroll
                for (int mt = 0; mt < 4; mt++)
                    #pragma unroll
                    for (int nt = 0; nt < 4; nt++)
                        mma_f16(acc[mt][nt], af[mt],
                                bfr[nt >> 1][(nt & 1) * 2], bfr[nt >> 1][(nt & 1) * 2 + 1]);
            }
            __syncthreads();
        }

        const int r_in = lane >> 2;
        const int c2 = (lane & 3) << 1;
        #pragma unroll
        for (int mt = 0; mt < 4; mt++) {
            int r0 = bm + warp_m * 64 + mt * 16 + r_in;
            #pragma unroll
            for (int nt = 0; nt < 4; nt++) {
                int c0 = bn + warp_n * 32 + nt * 8 + c2;
                float bx = bias[c0], by = bias[c0 + 1];
                float v00 = (acc[mt][nt][0] + bx) * cscale, v01 = (acc[mt][nt][1] + by) * cscale;
                float v10 = (acc[mt][nt][2] + bx) * cscale, v11 = (acc[mt][nt][3] + by) * cscale;
                if (half_out) {
                    uint32_t* Ch = (uint32_t*)C;
                    Ch[((size_t)r0 * D_MODEL + c0) >> 1]       = pack_h2(v00, v01);
                    Ch[((size_t)(r0 + 8) * D_MODEL + c0) >> 1] = pack_h2(v10, v11);
                } else {
                    float* Cf = (float*)C;
                    *reinterpret_cast<float2*>(Cf + (size_t)r0 * D_MODEL + c0) = make_float2(v00, v01);
                    *reinterpret_cast<float2*>(Cf + (size_t)(r0 + 8) * D_MODEL + c0) = make_float2(v10, v11);
                }
            }
        }
    }
}

// ---------------- fp16 mma causal flash attention (R10 64q shape) ----------------
__global__ __launch_bounds__(128) void attn_h(
    const __half* __restrict__ Q, const __half* __restrict__ K,
    const __half* __restrict__ V, __half* __restrict__ O)
{
    __shared__ __align__(1024) char smem_raw[40960];
    uint32_t sb = smem_u32(smem_raw);
    const uint32_t Qs = sb;                     // 8KB: 64q x 128B

    const int tid = threadIdx.x;
    const int lane = tid & 31;
    const int wid = tid >> 5;
    const int qt = blockIdx.x;
    const int h  = blockIdx.y;
    const int b  = blockIdx.z;

    const int Lg = lane >> 3;
    const int Lr = lane & 7;
    const int a_row = ((Lg & 1) << 3) + Lr;
    const int a_byte = (Lg >> 1) << 4;
    const int k_row = Lr + ((Lg >> 1) << 3);
    const int k_byte = (Lg & 1) << 4;
    const int v_row = Lr + ((Lg & 1) << 3);
    const int v_byte = (Lg >> 1) << 4;

    const int r_in = lane >> 2;
    const int c2 = (lane & 3) << 1;

    const __half* Qg = Q + ((size_t)(b * SEQ + qt * 64)) * D_MODEL + h * D_HEAD;

    #pragma unroll
    for (int i = 0; i < 4; i++) {
        int slot = tid + i * 128;
        int r = slot >> 3, j = slot & 7;
        cp_async16(Qs + sw128((uint32_t)(r * 128 + j * 16)), Qg + r * D_MODEL + j * 8);
    }
    cp_commit();

    auto issue_kv = [&](int kb) {
        uint32_t Kst = sb + 8192 + (kb & 1) * 16384;
        uint32_t Vst = Kst + 8192;
        const __half* Kg = K + ((size_t)(b * SEQ + kb * 64)) * D_MODEL + h * D_HEAD;
        const __half* Vg = V + ((size_t)(b * SEQ + kb * 64)) * D_MODEL + h * D_HEAD;
        #pragma unroll
        for (int i = 0; i < 4; i++) {
            int slot = tid + i * 128;
            int r = slot >> 3, j = slot & 7;
            uint32_t sw = sw128((uint32_t)(r * 128 + j * 16));
            cp_async16(Kst + sw, Kg + r * D_MODEL + j * 8);
            cp_async16(Vst + sw, Vg + r * D_MODEL + j * 8);
        }
        cp_commit();
    };
    issue_kv(0);

    cp_wait<1>();   // Q arrived
    __syncthreads();

    uint32_t qf[4][4];
    #pragma unroll
    for (int ks = 0; ks < 4; ks++)
        ldmatrix_x4(qf[ks], Qs + sw128(
            (uint32_t)((wid * 16 + a_row) * 128 + ks * 32 + a_byte)));

    float accv[8][4];
    #pragma unroll
    for (int nt = 0; nt < 8; nt++)
        #pragma unroll
        for (int e = 0; e < 4; e++) accv[nt][e] = 0.f;
    float m0 = -INFINITY, m1 = -INFINITY, l0 = 0.f, l1 = 0.f;

    for (int kb = 0; kb <= qt; kb++) {
        cp_wait<0>();
        __syncthreads();
        if (kb < qt) issue_kv(kb + 1);

        uint32_t Kst = sb + 8192 + (kb & 1) * 16384;
        uint32_t Vst = Kst + 8192;

        // ---- scores (base-2 logits; Q pre-scaled) ----
        float sc[8][4];
        #pragma unroll
        for (int nt = 0; nt < 8; nt++)
            #pragma unroll
            for (int e = 0; e < 4; e++) sc[nt][e] = 0.f;

        #pragma unroll
        for (int ks = 0; ks < 4; ks++) {
            #pragma unroll
            for (int kp = 0; kp < 4; kp++) {
                uint32_t kf[4];
                ldmatrix_x4(kf, Kst + sw128(
                    (uint32_t)((kp * 16 + k_row) * 128 + ks * 32 + k_byte)));
                mma_f16(sc[kp * 2],     qf[ks], kf[0], kf[1]);
                mma_f16(sc[kp * 2 + 1], qf[ks], kf[2], kf[3]);
            }
        }

        if (kb == qt) {
            int rg0 = qt * 64 + wid * 16 + r_in;
            int rg1 = rg0 + 8;
            #pragma unroll
            for (int nt = 0; nt < 8; nt++) {
                int cg = kb * 64 + nt * 8 + c2;
                if (cg     > rg0) sc[nt][0] = -INFINITY;
                if (cg + 1 > rg0) sc[nt][1] = -INFINITY;
                if (cg     > rg1) sc[nt][2] = -INFINITY;
                if (cg + 1 > rg1) sc[nt][3] = -INFINITY;
            }
        }

        // ---- online softmax (base 2) ----
        float mx0 = -INFINITY, mx1 = -INFINITY;
        #pragma unroll
        for (int nt = 0; nt < 8; nt++) {
            mx0 = fmaxf(mx0, fmaxf(sc[nt][0], sc[nt][1]));
            mx1 = fmaxf(mx1, fmaxf(sc[nt][2], sc[nt][3]));
        }
        mx0 = fmaxf(mx0, __shfl_xor_sync(0xffffffffu, mx0, 1));
        mx0 = fmaxf(mx0, __shfl_xor_sync(0xffffffffu, mx0, 2));
        mx1 = fmaxf(mx1, __shfl_xor_sync(0xffffffffu, mx1, 1));
        mx1 = fmaxf(mx1, __shfl_xor_sync(0xffffffffu, mx1, 2));

        float mn0 = fmaxf(m0, mx0), mn1 = fmaxf(m1, mx1);
        float cr0 = exp2f(m0 - mn0), cr1 = exp2f(m1 - mn1);
        m0 = mn0; m1 = mn1;
        #pragma unroll
        for (int nt = 0; nt < 8; nt++) {
            accv[nt][0] *= cr0; accv[nt][1] *= cr0;
            accv[nt][2] *= cr1; accv[nt][3] *= cr1;
        }
        float s0 = 0.f, s1 = 0.f;
        #pragma unroll
        for (int nt = 0; nt < 8; nt++) {
            sc[nt][0] = exp2f(sc[nt][0] - mn0);
            sc[nt][1] = exp2f(sc[nt][1] - mn0);
            sc[nt][2] = exp2f(sc[nt][2] - mn1);
            sc[nt][3] = exp2f(sc[nt][3] - mn1);
            s0 += sc[nt][0] + sc[nt][1];
            s1 += sc[nt][2] + sc[nt][3];
        }
        s0 += __shfl_xor_sync(0xffffffffu, s0, 1);
        s0 += __shfl_xor_sync(0xffffffffu, s0, 2);
        s1 += __shfl_xor_sync(0xffffffffu, s1, 1);
        s1 += __shfl_xor_sync(0xffffffffu, s1, 2);
        l0 = l0 * cr0 + s0;
        l1 = l1 * cr1 + s1;

        // ---- accv += P @ V ----
        #pragma unroll
        for (int ks2 = 0; ks2 < 4; ks2++) {
            uint32_t pf[4];
            pf[0] = pack_h2(sc[2*ks2][0],     sc[2*ks2][1]);
            pf[1] = pack_h2(sc[2*ks2][2],     sc[2*ks2][3]);
            pf[2] = pack_h2(sc[2*ks2 + 1][0], sc[2*ks2 + 1][1]);
            pf[3] = pack_h2(sc[2*ks2 + 1][2], sc[2*ks2 + 1][3]);
            #pragma unroll
            for (int dn = 0; dn < 4; dn++) {
                uint32_t vf[4];
                ldmatrix_x4_trans(vf, Vst + sw128(
                    (uint32_t)((ks2 * 16 + v_row) * 128 + dn * 32 + v_byte)));
                mma_f16(accv[dn * 2],     pf, vf[0], vf[1]);
                mma_f16(accv[dn * 2 + 1], pf, vf[2], vf[3]);
            }
        }
    }

    // ---- finalize ----
    float inv0 = 1.f / l0, inv1 = 1.f / l1;
    int r0 = qt * 64 + wid * 16 + r_in;
    uint32_t* Og = (uint32_t*)(O + ((size_t)(b * SEQ)) * D_MODEL + h * D_HEAD);
    #pragma unroll
    for (int nt = 0; nt < 8; nt++) {
        int c0 = nt * 8 + c2;
        Og[((size_t)r0 * D_MODEL + c0) >> 1]       = pack_h2(accv[nt][0] * inv0, accv[nt][1] * inv0);
        Og[((size_t)(r0 + 8) * D_MODEL + c0) >> 1] = pack_h2(accv[nt][2] * inv1, accv[nt][3] * inv1);
    }
}

// ---------------- launch ----------------
extern "C" void kernel_launch(void* const* d_in, const int* in_sizes, int n_in,
                              void* d_out, int out_size)
{
    const float* X        = (const float*)d_in[0];
    const float* ln_gamma = (const float*)d_in[1];
    const float* ln_beta  = (const float*)d_in[2];
    const float* Wq       = (const float*)d_in[3];
    const float* bq       = (const float*)d_in[4];
    const float* Wk       = (const float*)d_in[5];
    const float* bk       = (const float*)d_in[6];
    const float* Wv       = (const float*)d_in[7];
    const float* bv       = (const float*)d_in[8];
    const float* Wo       = (const float*)d_in[9];
    const float* bo       = (const float*)d_in[10];
    float* out = (float*)d_out;

    __half *Xn, *Qm, *Km, *Vm, *Om, *Wh;
    cudaGetSymbolAddress((void**)&Xn, g_Xn);
    cudaGetSymbolAddress((void**)&Qm, g_Q);
    cudaGetSymbolAddress((void**)&Km, g_K);
    cudaGetSymbolAddress((void**)&Vm, g_V);
    cudaGetSymbolAddress((void**)&Om, g_O);
    cudaGetSymbolAddress((void**)&Wh, g_Wh);

    const int gsmem = 3 * GSTG;   // 96KB (3-stage)
    cudaFuncSetAttribute(gemm_h, cudaFuncAttributeMaxDynamicSharedMemorySize, gsmem);

    ln_conv<<<M_ROWS + 1024, 256>>>(X, ln_gamma, ln_beta, Xn, Wq, Wk, Wv, Wo, Wh);

    // Q pre-scaled by (1/8)*log2(e) so attention softmax runs in base-2
    const float qscale = 0.125f * 1.44269504088896340736f;

    // fused persistent QKV: 1536 tiles over 296 CTAs
    gemm_h<<<NPERS, 256, gsmem>>>(Xn, Wh, 0, 1536, bq, bk, bv, Qm, Km, Vm, 1, qscale);

    dim3 agrid(SEQ / 64, N_HEADS, BATCH);
    attn_h<<<agrid, 128>>>(Qm, Km, Vm, Om);

    // persistent O-projection: 512 tiles over 296 CTAs
    gemm_h<<<NPERS, 256, gsmem>>>(Om, Wh, 3, 512, bo, bo, bo, out, out, out, 0, 1.0f);
}

// round 14
// speedup vs baseline: 1.2565x; 1.2565x over previous
#include <cuda_runtime.h>
#include <cuda_fp16.h>
#include <math.h>
#include <stdint.h>

#define D_MODEL 1024
#define N_HEADS 16
#define D_HEAD  64
#define BATCH   4
#define SEQ     2048
#define M_ROWS  (BATCH * SEQ)   // 8192

// ---------------- helpers ----------------
__device__ __forceinline__ uint32_t smem_u32(const void* p) {
    uint32_t a;
    asm("{ .reg .u64 t; cvta.to.shared.u64 t, %1; cvt.u32.u64 %0, t; }" : "=r"(a) : "l"(p));
    return a;
}
__device__ __forceinline__ uint32_t pack_h2(float lo, float hi) {
    uint32_t d; asm("cvt.rn.f16x2.f32 %0, %1, %2;" : "=r"(d) : "f"(hi), "f"(lo)); return d;
}
__device__ __forceinline__ void ldmatrix_x4(uint32_t* r, uint32_t addr) {
    asm volatile("ldmatrix.sync.aligned.m8n8.x4.shared.b16 {%0,%1,%2,%3}, [%4];"
        : "=r"(r[0]), "=r"(r[1]), "=r"(r[2]), "=r"(r[3]) : "r"(addr));
}
__device__ __forceinline__ void ldmatrix_x4_trans(uint32_t* r, uint32_t addr) {
    asm volatile("ldmatrix.sync.aligned.m8n8.x4.trans.shared.b16 {%0,%1,%2,%3}, [%4];"
        : "=r"(r[0]), "=r"(r[1]), "=r"(r[2]), "=r"(r[3]) : "r"(addr));
}
__device__ __forceinline__ void mma_f16(float* c, const uint32_t* a, uint32_t b0, uint32_t b1) {
    asm volatile("mma.sync.aligned.m16n8k16.row.col.f32.f16.f16.f32 "
        "{%0,%1,%2,%3}, {%4,%5,%6,%7}, {%8,%9}, {%0,%1,%2,%3};"
        : "+f"(c[0]), "+f"(c[1]), "+f"(c[2]), "+f"(c[3])
        : "r"(a[0]), "r"(a[1]), "r"(a[2]), "r"(a[3]), "r"(b0), "r"(b1));
}
__device__ __forceinline__ uint32_t sw128(uint32_t off) { return off ^ ((off >> 3) & 0x70); }
__device__ __forceinline__ void cp_async16(uint32_t s, const void* g) {
    asm volatile("cp.async.cg.shared.global [%0], [%1], 16;" :: "r"(s), "l"(g));
}
__device__ __forceinline__ void cp_commit() { asm volatile("cp.async.commit_group;" ::: "memory"); }
template<int N> __device__ __forceinline__ void cp_wait() {
    asm volatile("cp.async.wait_group %0;" :: "n"(N) : "memory");
}

// ---------------- scratch (half precision working set) ----------------
__device__ __half g_Xn[M_ROWS * D_MODEL];
__device__ __half g_Q [M_ROWS * D_MODEL];
__device__ __half g_K [M_ROWS * D_MODEL];
__device__ __half g_V [M_ROWS * D_MODEL];
__device__ __half g_O [M_ROWS * D_MODEL];
__device__ __half g_Wh[4 * D_MODEL * D_MODEL];   // Wq,Wk,Wv,Wo as fp16

// ---------------- fused LayerNorm + weight convert ----------------
__global__ __launch_bounds__(256) void ln_conv(
    const float* __restrict__ X, const float* __restrict__ gamma,
    const float* __restrict__ beta, __half* __restrict__ Xn,
    const float* __restrict__ Wq, const float* __restrict__ Wk,
    const float* __restrict__ Wv, const float* __restrict__ Wo,
    __half* __restrict__ Wh)
{
    int tid = threadIdx.x;
    if (blockIdx.x >= M_ROWS) {
        int idx = (blockIdx.x - M_ROWS) * 256 + tid;
        const float* src[4] = { Wq, Wk, Wv, Wo };
        #pragma unroll
        for (int w = 0; w < 4; w++) {
            float4 v = reinterpret_cast<const float4*>(src[w])[idx];
            uint2 o;
            o.x = pack_h2(v.x, v.y);
            o.y = pack_h2(v.z, v.w);
            reinterpret_cast<uint2*>(Wh + (size_t)w * D_MODEL * D_MODEL)[idx] = o;
        }
        return;
    }

    int row = blockIdx.x;
    const float4* xr = reinterpret_cast<const float4*>(X + (size_t)row * D_MODEL);
    float4 v = xr[tid];

    float s  = v.x + v.y + v.z + v.w;
    float sq = v.x*v.x + v.y*v.y + v.z*v.z + v.w*v.w;

    #pragma unroll
    for (int o = 16; o > 0; o >>= 1) {
        s  += __shfl_xor_sync(0xffffffffu, s,  o);
        sq += __shfl_xor_sync(0xffffffffu, sq, o);
    }
    __shared__ float ss[8], ssq[8];
    int wid = tid >> 5, lid = tid & 31;
    if (lid == 0) { ss[wid] = s; ssq[wid] = sq; }
    __syncthreads();
    if (wid == 0) {
        float a = (lid < 8) ? ss[lid]  : 0.f;
        float bb = (lid < 8) ? ssq[lid] : 0.f;
        #pragma unroll
        for (int o = 4; o > 0; o >>= 1) {
            a  += __shfl_xor_sync(0xffffffffu, a, o);
            bb += __shfl_xor_sync(0xffffffffu, bb, o);
        }
        if (lid == 0) { ss[0] = a; ssq[0] = bb; }
    }
    __syncthreads();
    float mean = ss[0] * (1.0f / D_MODEL);
    float var  = ssq[0] * (1.0f / D_MODEL) - mean * mean;
    float rstd = rsqrtf(var + 1e-5f);

    const float4* g4 = reinterpret_cast<const float4*>(gamma);
    const float4* b4 = reinterpret_cast<const float4*>(beta);
    float4 gv = g4[tid], bv = b4[tid];
    uint2 o;
    o.x = pack_h2((v.x - mean) * rstd * gv.x + bv.x, (v.y - mean) * rstd * gv.y + bv.y);
    o.y = pack_h2((v.z - mean) * rstd * gv.z + bv.z, (v.w - mean) * rstd * gv.w + bv.w);
    reinterpret_cast<uint2*>(Xn + (size_t)row * D_MODEL)[tid] = o;
}

// ---------------- fp16 mma GEMM: C = (A @ W^T + bias) * cscale ----------------
// 128x128 CTA tile, 128 threads, 4 warps of 64x64 (2m x 2n), BK=64,
// 3-stage cp.async (96KB), 2 CTAs/SM. 1.5x fewer smem fragment reads per FLOP
// than the 64x32 warp tile.
#define GSTG 32768   // stage = A tile 16KB + B tile 16KB

__global__ __launch_bounds__(128, 2) void gemm_h(
    const __half* __restrict__ A, const __half* __restrict__ Wh, int w_off,
    const float* __restrict__ bias0, const float* __restrict__ bias1, const float* __restrict__ bias2,
    void* __restrict__ C0, void* __restrict__ C1, void* __restrict__ C2,
    int half_out, float qscale)
{
    extern __shared__ char sm[];
    uint32_t sbase = smem_u32(sm);

    const int z = blockIdx.z;
    const __half* W = Wh + (size_t)(w_off + z) * D_MODEL * D_MODEL;
    const float* bias = (z == 0) ? bias0 : (z == 1) ? bias1 : bias2;
    void* C = (z == 0) ? C0 : (z == 1) ? C1 : C2;
    const float cscale = (z == 0) ? qscale : 1.0f;

    const int tid = threadIdx.x;
    const int lane = tid & 31;
    const int wid = tid >> 5;          // 0..3
    const int warp_m = wid >> 1;       // 0..1 -> 64-row slab
    const int warp_n = wid & 1;        // 0..1 -> 64-col slab
    const int bm = blockIdx.y * 128;
    const int bn = blockIdx.x * 128;

    const int Lg = lane >> 3;
    const int Lr = lane & 7;
    const int a_row = ((Lg & 1) << 3) + Lr;
    const int a_byte = (Lg >> 1) << 4;
    const int b_row = Lr + ((Lg >> 1) << 3);
    const int b_byte = (Lg & 1) << 4;

    float acc[4][8][4];
    #pragma unroll
    for (int mt = 0; mt < 4; mt++)
        #pragma unroll
        for (int nt = 0; nt < 8; nt++)
            #pragma unroll
            for (int e = 0; e < 4; e++) acc[mt][nt][e] = 0.f;

    // fill: 128 rows x 8 chunks(16B) per tile; 8 A-chunks + 8 B-chunks / thread
    auto issue = [&](int kt) {
        uint32_t sa = sbase + (kt % 3) * GSTG;
        uint32_t sb2 = sa + 16384;
        const __half* Ag = A + (size_t)bm * D_MODEL + kt * 64;
        const __half* Wg = W + (size_t)bn * D_MODEL + kt * 64;
        #pragma unroll
        for (int i = 0; i < 8; i++) {
            int slot = tid + i * 128;
            int r = slot >> 3, j = slot & 7;
            uint32_t sw = sw128((uint32_t)(r * 128 + j * 16));
            cp_async16(sa + sw, Ag + (size_t)r * D_MODEL + j * 8);
            cp_async16(sb2 + sw, Wg + (size_t)r * D_MODEL + j * 8);
        }
        cp_commit();
    };

    issue(0);
    issue(1);

    for (int kt = 0; kt < 16; kt++) {
        if (kt < 15) cp_wait<1>(); else cp_wait<0>();
        __syncthreads();
        if (kt + 2 < 16) issue(kt + 2);

        uint32_t abase = sbase + (kt % 3) * GSTG;
        uint32_t bbase = abase + 16384;

        #pragma unroll
        for (int ks = 0; ks < 4; ks++) {
            uint32_t af[4][4];
            #pragma unroll
            for (int mt = 0; mt < 4; mt++)
                ldmatrix_x4(af[mt], abase + sw128(
                    (uint32_t)((warp_m * 64 + mt * 16 + a_row) * 128 + ks * 32 + a_byte)));
            uint32_t bf[4][4];
            #pragma unroll
            for (int np = 0; np < 4; np++)
                ldmatrix_x4(bf[np], bbase + sw128(
                    (uint32_t)((warp_n * 64 + np * 16 + b_row) * 128 + ks * 32 + b_byte)));
            #pragma unroll
            for (int mt = 0; mt < 4; mt++)
                #pragma unroll
                for (int nt = 0; nt < 8; nt++)
                    mma_f16(acc[mt][nt], af[mt],
                            bf[nt >> 1][(nt & 1) * 2], bf[nt >> 1][(nt & 1) * 2 + 1]);
        }
        __syncthreads();
    }

    const int r_in = lane >> 2;
    const int c2 = (lane & 3) << 1;
    #pragma unroll
    for (int mt = 0; mt < 4; mt++) {
        int r0 = bm + warp_m * 64 + mt * 16 + r_in;
        #pragma unroll
        for (int nt = 0; nt < 8; nt++) {
            int c0 = bn + warp_n * 64 + nt * 8 + c2;
            float bx = bias[c0], by = bias[c0 + 1];
            float v00 = (acc[mt][nt][0] + bx) * cscale, v01 = (acc[mt][nt][1] + by) * cscale;
            float v10 = (acc[mt][nt][2] + bx) * cscale, v11 = (acc[mt][nt][3] + by) * cscale;
            if (half_out) {
                uint32_t* Ch = (uint32_t*)C;
                Ch[((size_t)r0 * D_MODEL + c0) >> 1]       = pack_h2(v00, v01);
                Ch[((size_t)(r0 + 8) * D_MODEL + c0) >> 1] = pack_h2(v10, v11);
            } else {
                float* Cf = (float*)C;
                *reinterpret_cast<float2*>(Cf + (size_t)r0 * D_MODEL + c0) = make_float2(v00, v01);
                *reinterpret_cast<float2*>(Cf + (size_t)(r0 + 8) * D_MODEL + c0) = make_float2(v10, v11);
            }
        }
    }
}

// ---------------- fp16 mma causal flash attention (R10 64q shape) ----------------
__global__ __launch_bounds__(128) void attn_h(
    const __half* __restrict__ Q, const __half* __restrict__ K,
    const __half* __restrict__ V, __half* __restrict__ O)
{
    __shared__ __align__(1024) char smem_raw[40960];
    uint32_t sb = smem_u32(smem_raw);
    const uint32_t Qs = sb;                     // 8KB: 64q x 128B

    const int tid = threadIdx.x;
    const int lane = tid & 31;
    const int wid = tid >> 5;
    const int qt = blockIdx.x;
    const int h  = blockIdx.y;
    const int b  = blockIdx.z;

    const int Lg = lane >> 3;
    const int Lr = lane & 7;
    const int a_row = ((Lg & 1) << 3) + Lr;
    const int a_byte = (Lg >> 1) << 4;
    const int k_row = Lr + ((Lg >> 1) << 3);
    const int k_byte = (Lg & 1) << 4;
    const int v_row = Lr + ((Lg & 1) << 3);
    const int v_byte = (Lg >> 1) << 4;

    const int r_in = lane >> 2;
    const int c2 = (lane & 3) << 1;

    const __half* Qg = Q + ((size_t)(b * SEQ + qt * 64)) * D_MODEL + h * D_HEAD;

    #pragma unroll
    for (int i = 0; i < 4; i++) {
        int slot = tid + i * 128;
        int r = slot >> 3, j = slot & 7;
        cp_async16(Qs + sw128((uint32_t)(r * 128 + j * 16)), Qg + r * D_MODEL + j * 8);
    }
    cp_commit();

    auto issue_kv = [&](int kb) {
        uint32_t Kst = sb + 8192 + (kb & 1) * 16384;
        uint32_t Vst = Kst + 8192;
        const __half* Kg = K + ((size_t)(b * SEQ + kb * 64)) * D_MODEL + h * D_HEAD;
        const __half* Vg = V + ((size_t)(b * SEQ + kb * 64)) * D_MODEL + h * D_HEAD;
        #pragma unroll
        for (int i = 0; i < 4; i++) {
            int slot = tid + i * 128;
            int r = slot >> 3, j = slot & 7;
            uint32_t sw = sw128((uint32_t)(r * 128 + j * 16));
            cp_async16(Kst + sw, Kg + r * D_MODEL + j * 8);
            cp_async16(Vst + sw, Vg + r * D_MODEL + j * 8);
        }
        cp_commit();
    };
    issue_kv(0);

    cp_wait<1>();   // Q arrived
    __syncthreads();

    uint32_t qf[4][4];
    #pragma unroll
    for (int ks = 0; ks < 4; ks++)
        ldmatrix_x4(qf[ks], Qs + sw128(
            (uint32_t)((wid * 16 + a_row) * 128 + ks * 32 + a_byte)));

    float accv[8][4];
    #pragma unroll
    for (int nt = 0; nt < 8; nt++)
        #pragma unroll
        for (int e = 0; e < 4; e++) accv[nt][e] = 0.f;
    float m0 = -INFINITY, m1 = -INFINITY, l0 = 0.f, l1 = 0.f;

    for (int kb = 0; kb <= qt; kb++) {
        cp_wait<0>();
        __syncthreads();
        if (kb < qt) issue_kv(kb + 1);

        uint32_t Kst = sb + 8192 + (kb & 1) * 16384;
        uint32_t Vst = Kst + 8192;

        // ---- scores (base-2 logits; Q pre-scaled) ----
        float sc[8][4];
        #pragma unroll
        for (int nt = 0; nt < 8; nt++)
            #pragma unroll
            for (int e = 0; e < 4; e++) sc[nt][e] = 0.f;

        #pragma unroll
        for (int ks = 0; ks < 4; ks++) {
            #pragma unroll
            for (int kp = 0; kp < 4; kp++) {
                uint32_t kf[4];
                ldmatrix_x4(kf, Kst + sw128(
                    (uint32_t)((kp * 16 + k_row) * 128 + ks * 32 + k_byte)));
                mma_f16(sc[kp * 2],     qf[ks], kf[0], kf[1]);
                mma_f16(sc[kp * 2 + 1], qf[ks], kf[2], kf[3]);
            }
        }

        if (kb == qt) {
            int rg0 = qt * 64 + wid * 16 + r_in;
            int rg1 = rg0 + 8;
            #pragma unroll
            for (int nt = 0; nt < 8; nt++) {
                int cg = kb * 64 + nt * 8 + c2;
                if (cg     > rg0) sc[nt][0] = -INFINITY;
                if (cg + 1 > rg0) sc[nt][1] = -INFINITY;
                if (cg     > rg1) sc[nt][2] = -INFINITY;
                if (cg + 1 > rg1) sc[nt][3] = -INFINITY;
            }
        }

        // ---- online softmax (base 2) ----
        float mx0 = -INFINITY, mx1 = -INFINITY;
        #pragma unroll
        for (int nt = 0; nt < 8; nt++) {
            mx0 = fmaxf(mx0, fmaxf(sc[nt][0], sc[nt][1]));
            mx1 = fmaxf(mx1, fmaxf(sc[nt][2], sc[nt][3]));
        }
        mx0 = fmaxf(mx0, __shfl_xor_sync(0xffffffffu, mx0, 1));
        mx0 = fmaxf(mx0, __shfl_xor_sync(0xffffffffu, mx0, 2));
        mx1 = fmaxf(mx1, __shfl_xor_sync(0xffffffffu, mx1, 1));
        mx1 = fmaxf(mx1, __shfl_xor_sync(0xffffffffu, mx1, 2));

        float mn0 = fmaxf(m0, mx0), mn1 = fmaxf(m1, mx1);
        float cr0 = exp2f(m0 - mn0), cr1 = exp2f(m1 - mn1);
        m0 = mn0; m1 = mn1;
        #pragma unroll
        for (int nt = 0; nt < 8; nt++) {
            accv[nt][0] *= cr0; accv[nt][1] *= cr0;
            accv[nt][2] *= cr1; accv[nt][3] *= cr1;
        }
        float s0 = 0.f, s1 = 0.f;
        #pragma unroll
        for (int nt = 0; nt < 8; nt++) {
            sc[nt][0] = exp2f(sc[nt][0] - mn0);
            sc[nt][1] = exp2f(sc[nt][1] - mn0);
            sc[nt][2] = exp2f(sc[nt][2] - mn1);
            sc[nt][3] = exp2f(sc[nt][3] - mn1);
            s0 += sc[nt][0] + sc[nt][1];
            s1 += sc[nt][2] + sc[nt][3];
        }
        s0 += __shfl_xor_sync(0xffffffffu, s0, 1);
        s0 += __shfl_xor_sync(0xffffffffu, s0, 2);
        s1 += __shfl_xor_sync(0xffffffffu, s1, 1);
        s1 += __shfl_xor_sync(0xffffffffu, s1, 2);
        l0 = l0 * cr0 + s0;
        l1 = l1 * cr1 + s1;

        // ---- accv += P @ V ----
        #pragma unroll
        for (int ks2 = 0; ks2 < 4; ks2++) {
            uint32_t pf[4];
            pf[0] = pack_h2(sc[2*ks2][0],     sc[2*ks2][1]);
            pf[1] = pack_h2(sc[2*ks2][2],     sc[2*ks2][3]);
            pf[2] = pack_h2(sc[2*ks2 + 1][0], sc[2*ks2 + 1][1]);
            pf[3] = pack_h2(sc[2*ks2 + 1][2], sc[2*ks2 + 1][3]);
            #pragma unroll
            for (int dn = 0; dn < 4; dn++) {
                uint32_t vf[4];
                ldmatrix_x4_trans(vf, Vst + sw128(
                    (uint32_t)((ks2 * 16 + v_row) * 128 + dn * 32 + v_byte)));
                mma_f16(accv[dn * 2],     pf, vf[0], vf[1]);
                mma_f16(accv[dn * 2 + 1], pf, vf[2], vf[3]);
            }
        }
    }

    // ---- finalize ----
    float inv0 = 1.f / l0, inv1 = 1.f / l1;
    int r0 = qt * 64 + wid * 16 + r_in;
    uint32_t* Og = (uint32_t*)(O + ((size_t)(b * SEQ)) * D_MODEL + h * D_HEAD);
    #pragma unroll
    for (int nt = 0; nt < 8; nt++) {
        int c0 = nt * 8 + c2;
        Og[((size_t)r0 * D_MODEL + c0) >> 1]       = pack_h2(accv[nt][0] * inv0, accv[nt][1] * inv0);
        Og[((size_t)(r0 + 8) * D_MODEL + c0) >> 1] = pack_h2(accv[nt][2] * inv1, accv[nt][3] * inv1);
    }
}

// ---------------- launch ----------------
extern "C" void kernel_launch(void* const* d_in, const int* in_sizes, int n_in,
                              void* d_out, int out_size)
{
    const float* X        = (const float*)d_in[0];
    const float* ln_gamma = (const float*)d_in[1];
    const float* ln_beta  = (const float*)d_in[2];
    const float* Wq       = (const float*)d_in[3];
    const float* bq       = (const float*)d_in[4];
    const float* Wk       = (const float*)d_in[5];
    const float* bk       = (const float*)d_in[6];
    const float* Wv       = (const float*)d_in[7];
    const float* bv       = (const float*)d_in[8];
    const float* Wo       = (const float*)d_in[9];
    const float* bo       = (const float*)d_in[10];
    float* out = (float*)d_out;

    __half *Xn, *Qm, *Km, *Vm, *Om, *Wh;
    cudaGetSymbolAddress((void**)&Xn, g_Xn);
    cudaGetSymbolAddress((void**)&Qm, g_Q);
    cudaGetSymbolAddress((void**)&Km, g_K);
    cudaGetSymbolAddress((void**)&Vm, g_V);
    cudaGetSymbolAddress((void**)&Om, g_O);
    cudaGetSymbolAddress((void**)&Wh, g_Wh);

    const int gsmem = 3 * GSTG;   // 96KB (3-stage)
    cudaFuncSetAttribute(gemm_h, cudaFuncAttributeMaxDynamicSharedMemorySize, gsmem);

    ln_conv<<<M_ROWS + 1024, 256>>>(X, ln_gamma, ln_beta, Xn, Wq, Wk, Wv, Wo, Wh);

    // Q pre-scaled by (1/8)*log2(e) so attention softmax runs in base-2
    const float qscale = 0.125f * 1.44269504088896340736f;
    dim3 qkv_grid(D_MODEL / 128, M_ROWS / 128, 3);
    gemm_h<<<qkv_grid, 128, gsmem>>>(Xn, Wh, 0, bq, bk, bv, Qm, Km, Vm, 1, qscale);

    dim3 agrid(SEQ / 64, N_HEADS, BATCH);
    attn_h<<<agrid, 128>>>(Qm, Km, Vm, Om);

    dim3 o_grid(D_MODEL / 128, M_ROWS / 128, 1);
    gemm_h<<<o_grid, 128, gsmem>>>(Om, Wh, 3, bo, bo, bo, out, out, out, 0, 1.0f);
}